// round 14
// baseline (speedup 1.0000x reference)
#include <cuda_runtime.h>
#include <cuda_fp16.h>
#include <cstdint>

// GlobalPoolDistance: patch-RBF MMD, single fused persistent kernel (R14).
// f16 mma.sync m16n8k16 (f16 accumulate) computes the exp2 argument directly:
//   A row i = [C2*a_0..C2*a_26, 1, -u_i, 0..]   (u = ||a||^2 * log2e/SIG2)
//   B row j = [b_0..b_26,      -v_j, 1, 0..]
//   acc(i,j) = C2*<a,b> - u - v = -log2e*||a-b||^2/SIG2 ; K = exp2(acc).
// R14: dual-pipe tiles. Per warp, cols 0-55 of its 64-col slice go through
// the tensor pipe (28 MMA, rt16); cols 56-63 are computed on the idle FMA
// pipe with HFMA2 (even/odd-k partial sums in one half2; arg = x + y;
// guard max(x,y) > -15 soundly implies arg > -30). Warp parity staggers
// the phase order so both pipes stay fed on each SMSP.
// Epilogue skip threshold -30; diagonal tiles force the epilogue;
// diagonals replaced positionally by exact 1.0; pads self-screen.

#define TILE 128
#define NPATCH 3844
#define NTILES 31
#define NROWS (NTILES * TILE)                     // 3968
#define BATCH 8
#define ROW_U4 4                                  // 64 B per staged row (32 f16)
#define STAGE_U4 (4 * BATCH * NROWS * ROW_U4)
#define CHUNKS 2208                               // 992 xy + 1216 sym
#define WORKERS 296
#define STAGE_TASKS (2 * BATCH * NROWS)           // 63488

// dynamic smem layout
#define SMEM_A_OFF   0                            // 8 KB A tile
#define SMEM_B_OFF   8192                         // 8 slots x 8 KB
#define SMEM_RED_OFF (8192 + 8 * 8192)            // 73728
#define SMEM_TKT_OFF (SMEM_RED_OFF + 32)
#define SMEM_LST_OFF (SMEM_TKT_OFF + 4)
#define SMEM_BYTES   (SMEM_LST_OFF + 4 + 24)

__device__ uint4 g_stage[STAGE_U4];
__device__ float g_partials[WORKERS];
__device__ unsigned int g_bar1;
__device__ unsigned int g_ticket;
__device__ unsigned int g_done;

__device__ __forceinline__ uint32_t smem_to_u32(const void* p) {
    uint32_t a;
    asm("{ .reg .u64 t; cvta.to.shared.u64 t, %1; cvt.u32.u64 %0, t; }"
        : "=r"(a) : "l"(p));
    return a;
}
__device__ __forceinline__ void cp_async16(uint32_t smem, const void* gptr) {
    asm volatile("cp.async.cg.shared.global [%0], [%1], 16;"
                 :: "r"(smem), "l"(gptr) : "memory");
}
#define CP_COMMIT() asm volatile("cp.async.commit_group;" ::: "memory")
#define CP_WAIT0()  asm volatile("cp.async.wait_group 0;" ::: "memory")

__device__ __forceinline__ void ldsm_x4(uint32_t& r0, uint32_t& r1,
                                        uint32_t& r2, uint32_t& r3, uint32_t a) {
    asm volatile("ldmatrix.sync.aligned.m8n8.x4.shared.b16 {%0,%1,%2,%3}, [%4];"
                 : "=r"(r0), "=r"(r1), "=r"(r2), "=r"(r3) : "r"(a));
}
__device__ __forceinline__ void lds128(uint4& v, uint32_t a) {
    asm volatile("ld.shared.v4.u32 {%0,%1,%2,%3}, [%4];"
                 : "=r"(v.x), "=r"(v.y), "=r"(v.z), "=r"(v.w) : "r"(a));
}
__device__ __forceinline__ void mma_h(uint32_t* d, const uint32_t* a,
                                      uint32_t b0, uint32_t b1) {
    asm volatile("mma.sync.aligned.m16n8k16.row.col.f16.f16.f16.f16 "
                 "{%0,%1}, {%2,%3,%4,%5}, {%6,%7}, {%0,%1};"
                 : "+r"(d[0]), "+r"(d[1])
                 : "r"(a[0]), "r"(a[1]), "r"(a[2]), "r"(a[3]), "r"(b0), "r"(b1));
}
__device__ __forceinline__ uint32_t pkh(float a, float b) {
    __half2 h = __floats2half2_rn(a, b);
    return *reinterpret_cast<uint32_t*>(&h);
}
__device__ __forceinline__ uint32_t hmax2u(uint32_t a, uint32_t b) {
    __half2 r = __hmax2(*reinterpret_cast<__half2*>(&a),
                        *reinterpret_cast<__half2*>(&b));
    return *reinterpret_cast<uint32_t*>(&r);
}
__device__ __forceinline__ uint32_t hfma2u(uint32_t a, uint32_t b, uint32_t c) {
    __half2 r = __hfma2(*reinterpret_cast<__half2*>(&a),
                        *reinterpret_cast<__half2*>(&b),
                        *reinterpret_cast<__half2*>(&c));
    return *reinterpret_cast<uint32_t*>(&r);
}

extern __shared__ __align__(1024) char dsm[];

__global__ void __launch_bounds__(256, 2)
mmd_fused(const float* __restrict__ x, const float* __restrict__ y,
          float* __restrict__ out) {
    const int tid = threadIdx.x;
    const int wid = tid >> 5;
    const int lane = tid & 31;

    float* red = reinterpret_cast<float*>(dsm + SMEM_RED_OFF);
    unsigned int* tkt = reinterpret_cast<unsigned int*>(dsm + SMEM_TKT_OFF);
    unsigned int* lst = reinterpret_cast<unsigned int*>(dsm + SMEM_LST_OFF);

    const float K1f = 4.9479492581208223f;        // log2e / 0.2916
    const float C2f = 9.8958985162416446f;        // 2*log2e / 0.2916

    // ================= Phase 1: stage f16 operand rows =================
    {
        int gtid = blockIdx.x * 256 + tid;
        if (gtid < STAGE_TASKS) {
            int n = gtid % NROWS;
            int t2 = gtid / NROWS;
            int b = t2 & 7;
            int img = t2 >> 3;
            const float* im = img ? y : x;

            float rv[27];
            float u = 0.0f;
            bool valid = (n < NPATCH);
            if (valid) {
                int i = n / 62;
                int j = n - i * 62;
                const float* p = im + b * 12288 + (i << 6) + j;
                float sq = 0.0f;
                #pragma unroll
                for (int c = 0; c < 3; c++)
                    #pragma unroll
                    for (int rr = 0; rr < 3; rr++)
                        #pragma unroll
                        for (int ss = 0; ss < 3; ss++) {
                            float v = p[c * 4096 + (rr << 6) + ss];
                            sq = fmaf(v, v, sq);
                            rv[c * 9 + rr * 3 + ss] = v;
                        }
                u = sq * K1f;
            } else {
                #pragma unroll
                for (int k = 0; k < 27; k++) rv[k] = 0.0f;
            }
            uint32_t sw = (uint32_t)(n >> 1) & 3u;

            #pragma unroll
            for (int form = 0; form < 2; form++) {
                float rowv[32];
                #pragma unroll
                for (int k = 0; k < 27; k++)
                    rowv[k] = form ? rv[k] : (C2f * rv[k]);
                float nu = valid ? -u : -60000.0f;   // fp16-range pad sentinel
                if (form) { rowv[27] = nu;   rowv[28] = 1.0f; }
                else      { rowv[27] = 1.0f; rowv[28] = nu;   }
                rowv[29] = rowv[30] = rowv[31] = 0.0f;
                uint32_t wds[16];
                #pragma unroll
                for (int q = 0; q < 16; q++)
                    wds[q] = pkh(rowv[2*q], rowv[2*q+1]);
                int ver = form * 2 + img;
                int base = ((ver * BATCH + b) * NROWS + n) * ROW_U4;
                #pragma unroll
                for (int c = 0; c < 4; c++)
                    g_stage[base + (c ^ sw)] =
                        make_uint4(wds[4*c], wds[4*c+1], wds[4*c+2], wds[4*c+3]);
            }
        }
        __threadfence();
        __syncthreads();
        if (tid == 0) {
            atomicAdd(&g_bar1, 1u);
            unsigned int v;
            do {
                asm volatile("ld.acquire.gpu.global.u32 %0, [%1];"
                             : "=r"(v) : "l"(&g_bar1));
                if (v >= WORKERS) break;
                __nanosleep(64);
            } while (true);
        }
        __syncthreads();
        __threadfence();
    }

    // ================= Phase 2: persistent tile loop =================
    const int mg = wid & 3;          // A rows mg*32..+31
    const int ng = wid >> 2;         // B rows ng*64..+63
    const uint32_t a_base = smem_to_u32(dsm) + SMEM_A_OFF;
    const uint32_t b_ring = smem_to_u32(dsm) + SMEM_B_OFF;   // 8 x 8192 B

    uint32_t offA[2][2];
    #pragma unroll
    for (int mt = 0; mt < 2; mt++)
        #pragma unroll
        for (int k = 0; k < 2; k++) {
            int rowA = mg * 32 + mt * 16 + (lane & 15);
            int ch = k * 2 + (lane >> 4);
            int swz = ch ^ ((rowA >> 1) & 3);
            offA[mt][k] = (uint32_t)(rowA * 64 + swz * 16);
        }
    uint32_t offB[2];
    #pragma unroll
    for (int k = 0; k < 2; k++) {
        int rloc = (lane & 7) + ((lane >> 4) << 3);
        int rowB = ng * 64 + rloc;
        int ch = k * 2 + ((lane >> 3) & 1);
        int swz = ch ^ ((rowB >> 1) & 3);
        offB[k] = (uint32_t)(rowB * 64 + swz * 16);
    }
    // scalar-path A row for this lane (rows mg*32 + lane)
    const int rowS = mg * 32 + lane;
    uint32_t offAS[4];
    #pragma unroll
    for (int kc = 0; kc < 4; kc++)
        offAS[kc] = (uint32_t)(rowS * 64 + ((kc ^ ((rowS >> 1) & 3)) * 16));

    float s = 0.0f;
    uint32_t af[2][2][4];

    auto compute_tile = [&](int slot, int ti, int tj, bool sym) {
        const uint32_t bb = b_ring + (uint32_t)(slot * 8192);
        uint32_t acc[2][7][2];      // tensor: 7 n8-blocks (cols 0..55 of slice)
        uint32_t sacc[8];           // scalar: cols 56..63 of slice, half2 partial sums

        auto do_tensor = [&]() {
            #pragma unroll
            for (int mt = 0; mt < 2; mt++)
                #pragma unroll
                for (int nt = 0; nt < 7; nt++)
                    acc[mt][nt][0] = acc[mt][nt][1] = 0u;
            #pragma unroll
            for (int k = 0; k < 2; k++)
                #pragma unroll
                for (int p = 0; p < 4; p++) {
                    uint32_t b0, b1, b2, b3;
                    ldsm_x4(b0, b1, b2, b3, bb + offB[k] + (uint32_t)(p * 1024));
                    mma_h(acc[0][2*p], af[0][k], b0, b1);
                    mma_h(acc[1][2*p], af[1][k], b0, b1);
                    if (2*p + 1 < 7) {
                        mma_h(acc[0][2*p+1], af[0][k], b2, b3);
                        mma_h(acc[1][2*p+1], af[1][k], b2, b3);
                    }
                }
        };
        auto do_scalar = [&]() {
            #pragma unroll
            for (int cc = 0; cc < 8; cc++) sacc[cc] = 0u;
            const int rowB0 = ng * 64 + 56;
            #pragma unroll
            for (int kc = 0; kc < 4; kc++) {
                uint4 av;
                lds128(av, a_base + offAS[kc]);
                #pragma unroll
                for (int cc = 0; cc < 8; cc++) {
                    int rb = rowB0 + cc;
                    uint4 bv;
                    lds128(bv, bb + (uint32_t)(rb * 64 + ((kc ^ ((rb >> 1) & 3)) * 16)));
                    sacc[cc] = hfma2u(av.x, bv.x, sacc[cc]);
                    sacc[cc] = hfma2u(av.y, bv.y, sacc[cc]);
                    sacc[cc] = hfma2u(av.z, bv.z, sacc[cc]);
                    sacc[cc] = hfma2u(av.w, bv.w, sacc[cc]);
                }
            }
        };
        if (wid & 1) { do_scalar(); do_tensor(); }
        else         { do_tensor(); do_scalar(); }

        bool diagTile = sym && (tj == ti);

        // tensor guard: max over 28 packed regs
        uint32_t m7[7];
        #pragma unroll
        for (int nt = 0; nt < 7; nt++)
            m7[nt] = hmax2u(hmax2u(acc[0][nt][0], acc[0][nt][1]),
                            hmax2u(acc[1][nt][0], acc[1][nt][1]));
        uint32_t mT = m7[0];
        #pragma unroll
        for (int nt = 1; nt < 7; nt++) mT = hmax2u(mT, m7[nt]);
        __half2 hmT = *reinterpret_cast<__half2*>(&mT);
        float mx_t = fmaxf(__low2float(hmT), __high2float(hmT));

        // scalar guard: max over 8 half2 partial sums (halves threshold -15)
        uint32_t mS = hmax2u(hmax2u(hmax2u(sacc[0], sacc[1]),
                                    hmax2u(sacc[2], sacc[3])),
                             hmax2u(hmax2u(sacc[4], sacc[5]),
                                    hmax2u(sacc[6], sacc[7])));
        __half2 hmS = *reinterpret_cast<__half2*>(&mS);
        float mx_s = fmaxf(__low2float(hmS), __high2float(hmS));

        if (diagTile || __any_sync(0xffffffffu, (mx_t > -30.0f) || (mx_s > -15.0f))) {
            float w = sym ? ((tj == ti) ? 1.0f : 2.0f) : -2.0f;
            float ts = 0.0f;
            // tensor epilogue (cols 0..55 of slice)
            int rbase = mg * 32 + (lane >> 2);
            int cbase = ng * 64 + ((lane & 3) << 1);
            #pragma unroll
            for (int mt = 0; mt < 2; mt++)
                #pragma unroll
                for (int nt = 0; nt < 7; nt++)
                    #pragma unroll
                    for (int r = 0; r < 2; r++) {
                        int rl = rbase + mt * 16 + (r << 3);
                        __half2 hv = *reinterpret_cast<__half2*>(&acc[mt][nt][r]);
                        float a0 = __low2float(hv);
                        float a1 = __high2float(hv);
                        int cl0 = cbase + nt * 8;
                        bool ok = (ti * TILE + rl < NPATCH);
                        bool d0 = diagTile && ok && (rl == cl0);
                        bool d1 = diagTile && ok && (rl == cl0 + 1);
                        float e0, e1;
                        asm("ex2.approx.ftz.f32 %0, %1;" : "=f"(e0) : "f"(a0));
                        asm("ex2.approx.ftz.f32 %0, %1;" : "=f"(e1) : "f"(a1));
                        ts += (d0 ? 1.0f : e0) + (d1 ? 1.0f : e1);
                    }
            // scalar epilogue (cols 56..63 of slice): arg = x + y
            bool okS = (ti * TILE + rowS < NPATCH);
            #pragma unroll
            for (int cc = 0; cc < 8; cc++) {
                __half2 hv = *reinterpret_cast<__half2*>(&sacc[cc]);
                float arg = __low2float(hv) + __high2float(hv);
                int clS = ng * 64 + 56 + cc;
                bool isd = diagTile && okS && (rowS == clS);
                float e;
                asm("ex2.approx.ftz.f32 %0, %1;" : "=f"(e) : "f"(arg));
                ts += isd ? 1.0f : e;
            }
            s = fmaf(w, ts, s);
        }
    };

    // load `cnt` B tiles into ring slots slot0..
    auto loadB = [&](const uint4* bbase, int tj0b, int cnt, int slot0) {
        for (int t = 0; t < cnt; t++) {
            const uint4* bs = bbase + ((tj0b + t) * TILE) * ROW_U4;
            uint32_t dst = b_ring + (uint32_t)((slot0 + t) * 8192);
            cp_async16(dst + (uint32_t)(tid * 16), bs + tid);
            cp_async16(dst + (uint32_t)((tid + 256) * 16), bs + tid + 256);
        }
    };

    for (;;) {
        __syncthreads();
        if (tid == 0) *tkt = atomicAdd(&g_ticket, 1u);
        __syncthreads();
        unsigned int c = *tkt;
        if (c >= CHUNKS) break;

        // ---- decode 8-tile chunk (128x128 tiles) ----
        int ti, tj0, len, verA, verB, b;
        bool sym;
        if (c < 992u) {
            int seg = c >> 2, q = c & 3;
            b = seg / 31; ti = seg - b * 31;
            tj0 = q * 8; len = (q < 3) ? 8 : 7;
            sym = false; verA = 0; verB = 3;
        } else {
            int d = (int)c - 992;
            int g = d / 76;
            int r = d - g * 76;
            int kind = g >> 3; b = g & 7;
            if (r < 8)       { ti = r;              tj0 = 0; }
            else if (r < 24) { int q = r - 8;  ti = 8  + (q >> 1); tj0 = (q & 1) * 8; }
            else if (r < 48) { int q = r - 24; int qd = q / 3; ti = 16 + qd; tj0 = (q - qd * 3) * 8; }
            else             { int q = r - 48; ti = 24 + (q >> 2); tj0 = (q & 3) * 8; }
            len = min(8, ti + 1 - tj0);
            sym = true; verA = kind; verB = 2 + kind;
        }

        const uint4* bbase = g_stage + ((verB * BATCH + b) * NROWS) * ROW_U4;

        // ---- prologue: A + first window (up to 4 B tiles) ----
        {
            const uint4* asrc = g_stage + ((verA * BATCH + b) * NROWS + ti * TILE) * ROW_U4;
            cp_async16(a_base + (uint32_t)(tid * 16), asrc + tid);
            cp_async16(a_base + (uint32_t)((tid + 256) * 16), asrc + tid + 256);
            loadB(bbase, tj0, min(len, 4), 0);
            CP_COMMIT();
        }

        int grp = 0;
        for (int w0 = 0; w0 < len; w0 += 4, grp ^= 1) {
            CP_WAIT0();
            __syncthreads();
            int nxt = w0 + 4;
            if (nxt < len) {
                loadB(bbase, tj0 + nxt, min(4, len - nxt), (grp ^ 1) * 4);
                CP_COMMIT();
            }
            if (w0 == 0) {
                #pragma unroll
                for (int mt = 0; mt < 2; mt++)
                    #pragma unroll
                    for (int k = 0; k < 2; k++)
                        ldsm_x4(af[mt][k][0], af[mt][k][1], af[mt][k][2], af[mt][k][3],
                                a_base + offA[mt][k]);
            }
            int s0 = grp * 4;
            int rem = len - w0;
            if (rem >= 4) {
                compute_tile(s0,     ti, tj0 + w0,     sym);
                compute_tile(s0 + 1, ti, tj0 + w0 + 1, sym);
                compute_tile(s0 + 2, ti, tj0 + w0 + 2, sym);
                compute_tile(s0 + 3, ti, tj0 + w0 + 3, sym);
            } else {
                for (int t = 0; t < rem; t++)
                    compute_tile(s0 + t, ti, tj0 + w0 + t, sym);
            }
        }
    }

    // ================= Phase 3: reduce + finalize =================
    #pragma unroll
    for (int o = 16; o; o >>= 1) s += __shfl_xor_sync(0xffffffffu, s, o);
    if (lane == 0) red[wid] = s;
    __syncthreads();
    if (tid == 0) {
        float tot = 0.0f;
        #pragma unroll
        for (int i2 = 0; i2 < 8; i2++) tot += red[i2];
        g_partials[blockIdx.x] = tot;
        __threadfence();
        unsigned int old = atomicAdd(&g_done, 1u);
        *lst = (old == WORKERS - 1) ? 1u : 0u;
    }
    __syncthreads();
    if (*lst) {
        __threadfence();
        float v = 0.0f;
        for (int i = tid; i < WORKERS; i += 256) v += g_partials[i];
        #pragma unroll
        for (int o = 16; o; o >>= 1) v += __shfl_xor_sync(0xffffffffu, v, o);
        if (lane == 0) red[wid] = v;
        __syncthreads();
        if (tid == 0) {
            float tot = 0.0f;
            #pragma unroll
            for (int i2 = 0; i2 < 8; i2++) tot += red[i2];
            out[0] = tot * (float)(1.0 / (8.0 * 3844.0 * 3844.0));
            g_bar1 = 0u;
            g_ticket = 0u;
            __threadfence();
            g_done = 0u;
        }
    }
}

extern "C" void kernel_launch(void* const* d_in, const int* in_sizes, int n_in,
                              void* d_out, int out_size) {
    const float* x = (const float*)d_in[0];
    const float* y = (const float*)d_in[1];
    cudaFuncSetAttribute(mmd_fused,
                         cudaFuncAttributeMaxDynamicSharedMemorySize, SMEM_BYTES);
    mmd_fused<<<WORKERS, 256, SMEM_BYTES>>>(x, y, (float*)d_out);
}

// round 15
// speedup vs baseline: 2.3117x; 2.3117x over previous
#include <cuda_runtime.h>
#include <cuda_fp16.h>
#include <cstdint>

// GlobalPoolDistance: patch-RBF MMD, single fused persistent kernel (R15).
// f16 mma.sync m16n8k16 (f16 accumulate) computes the exp2 argument directly:
//   A row i = [C2*a_0..C2*a_26, 1, -u_i, 0..]   (u = ||a||^2 * log2e/SIG2)
//   B row j = [b_0..b_26,      -v_j, 1, 0..]
//   acc(i,j) = C2*<a,b> - u - v = -log2e*||a-b||^2/SIG2 ; K = exp2(acc).
// Epilogue skip threshold -30 (deterministic per-term bound, see R7);
// diagonal tiles force the epilogue; diagonals replaced by exact 1.0.
// R15 = R13 (best) + edge-tile MMA skipping: strips ti==30 / tj==30 are
// >=97% padding (NPATCH=3844=30*128+4); their all-pad 16x8 blocks skip the
// MMA entirely (acc preset to -inf -> exp2 0, guard inert). Tensor-pipe
// slack freed by one CTA's warps is absorbed by the co-resident CTA.

#define TILE 128
#define NPATCH 3844
#define NTILES 31
#define NROWS (NTILES * TILE)                     // 3968
#define BATCH 8
#define ROW_U4 4                                  // 64 B per staged row (32 f16)
#define STAGE_U4 (4 * BATCH * NROWS * ROW_U4)
#define CHUNKS 2208                               // 992 xy + 1216 sym
#define WORKERS 296
#define STAGE_TASKS (2 * BATCH * NROWS)           // 63488

// dynamic smem layout
#define SMEM_A_OFF   0                            // 8 KB A tile
#define SMEM_B_OFF   8192                         // 8 slots x 8 KB
#define SMEM_RED_OFF (8192 + 8 * 8192)            // 73728
#define SMEM_TKT_OFF (SMEM_RED_OFF + 32)
#define SMEM_LST_OFF (SMEM_TKT_OFF + 4)
#define SMEM_BYTES   (SMEM_LST_OFF + 4 + 24)

#define NEGINF2 0xFC00FC00u                       // packed half2 (-inf, -inf)

__device__ uint4 g_stage[STAGE_U4];
__device__ float g_partials[WORKERS];
__device__ unsigned int g_bar1;
__device__ unsigned int g_ticket;
__device__ unsigned int g_done;

__device__ __forceinline__ uint32_t smem_to_u32(const void* p) {
    uint32_t a;
    asm("{ .reg .u64 t; cvta.to.shared.u64 t, %1; cvt.u32.u64 %0, t; }"
        : "=r"(a) : "l"(p));
    return a;
}
__device__ __forceinline__ void cp_async16(uint32_t smem, const void* gptr) {
    asm volatile("cp.async.cg.shared.global [%0], [%1], 16;"
                 :: "r"(smem), "l"(gptr) : "memory");
}
#define CP_COMMIT() asm volatile("cp.async.commit_group;" ::: "memory")
#define CP_WAIT0()  asm volatile("cp.async.wait_group 0;" ::: "memory")

__device__ __forceinline__ void ldsm_x4(uint32_t& r0, uint32_t& r1,
                                        uint32_t& r2, uint32_t& r3, uint32_t a) {
    asm volatile("ldmatrix.sync.aligned.m8n8.x4.shared.b16 {%0,%1,%2,%3}, [%4];"
                 : "=r"(r0), "=r"(r1), "=r"(r2), "=r"(r3) : "r"(a));
}
// f16 MMA with f16 accumulate: C fragment = 2 packed f16x2 regs.
__device__ __forceinline__ void mma_h(uint32_t* d, const uint32_t* a,
                                      uint32_t b0, uint32_t b1) {
    asm volatile("mma.sync.aligned.m16n8k16.row.col.f16.f16.f16.f16 "
                 "{%0,%1}, {%2,%3,%4,%5}, {%6,%7}, {%0,%1};"
                 : "+r"(d[0]), "+r"(d[1])
                 : "r"(a[0]), "r"(a[1]), "r"(a[2]), "r"(a[3]), "r"(b0), "r"(b1));
}
__device__ __forceinline__ uint32_t pkh(float a, float b) {
    __half2 h = __floats2half2_rn(a, b);
    return *reinterpret_cast<uint32_t*>(&h);
}
__device__ __forceinline__ uint32_t hmax2u(uint32_t a, uint32_t b) {
    __half2 r = __hmax2(*reinterpret_cast<__half2*>(&a),
                        *reinterpret_cast<__half2*>(&b));
    return *reinterpret_cast<uint32_t*>(&r);
}

extern __shared__ __align__(1024) char dsm[];

__global__ void __launch_bounds__(256, 2)
mmd_fused(const float* __restrict__ x, const float* __restrict__ y,
          float* __restrict__ out) {
    const int tid = threadIdx.x;
    const int wid = tid >> 5;
    const int lane = tid & 31;

    float* red = reinterpret_cast<float*>(dsm + SMEM_RED_OFF);
    unsigned int* tkt = reinterpret_cast<unsigned int*>(dsm + SMEM_TKT_OFF);
    unsigned int* lst = reinterpret_cast<unsigned int*>(dsm + SMEM_LST_OFF);

    const float K1f = 4.9479492581208223f;        // log2e / 0.2916
    const float C2f = 9.8958985162416446f;        // 2*log2e / 0.2916

    // ================= Phase 1: stage f16 operand rows =================
    {
        int gtid = blockIdx.x * 256 + tid;
        if (gtid < STAGE_TASKS) {
            int n = gtid % NROWS;
            int t2 = gtid / NROWS;
            int b = t2 & 7;
            int img = t2 >> 3;
            const float* im = img ? y : x;

            float rv[27];
            float u = 0.0f;
            bool valid = (n < NPATCH);
            if (valid) {
                int i = n / 62;
                int j = n - i * 62;
                const float* p = im + b * 12288 + (i << 6) + j;
                float sq = 0.0f;
                #pragma unroll
                for (int c = 0; c < 3; c++)
                    #pragma unroll
                    for (int rr = 0; rr < 3; rr++)
                        #pragma unroll
                        for (int ss = 0; ss < 3; ss++) {
                            float v = p[c * 4096 + (rr << 6) + ss];
                            sq = fmaf(v, v, sq);
                            rv[c * 9 + rr * 3 + ss] = v;
                        }
                u = sq * K1f;
            } else {
                #pragma unroll
                for (int k = 0; k < 27; k++) rv[k] = 0.0f;
            }
            uint32_t sw = (uint32_t)(n >> 1) & 3u;

            #pragma unroll
            for (int form = 0; form < 2; form++) {
                float rowv[32];
                #pragma unroll
                for (int k = 0; k < 27; k++)
                    rowv[k] = form ? rv[k] : (C2f * rv[k]);
                float nu = valid ? -u : -60000.0f;   // fp16-range pad sentinel
                if (form) { rowv[27] = nu;   rowv[28] = 1.0f; }
                else      { rowv[27] = 1.0f; rowv[28] = nu;   }
                rowv[29] = rowv[30] = rowv[31] = 0.0f;
                uint32_t wds[16];
                #pragma unroll
                for (int q = 0; q < 16; q++)
                    wds[q] = pkh(rowv[2*q], rowv[2*q+1]);
                int ver = form * 2 + img;
                int base = ((ver * BATCH + b) * NROWS + n) * ROW_U4;
                #pragma unroll
                for (int c = 0; c < 4; c++)
                    g_stage[base + (c ^ sw)] =
                        make_uint4(wds[4*c], wds[4*c+1], wds[4*c+2], wds[4*c+3]);
            }
        }
        __threadfence();
        __syncthreads();
        if (tid == 0) {
            atomicAdd(&g_bar1, 1u);
            unsigned int v;
            do {
                asm volatile("ld.acquire.gpu.global.u32 %0, [%1];"
                             : "=r"(v) : "l"(&g_bar1));
                if (v >= WORKERS) break;
                __nanosleep(64);
            } while (true);
        }
        __syncthreads();
        __threadfence();
    }

    // ================= Phase 2: persistent tile loop =================
    const int mg = wid & 3;          // A rows mg*32..+31
    const int ng = wid >> 2;         // B rows ng*64..+63
    const uint32_t a_base = smem_to_u32(dsm) + SMEM_A_OFF;
    const uint32_t b_ring = smem_to_u32(dsm) + SMEM_B_OFF;   // 8 x 8192 B

    uint32_t offA[2][2];
    #pragma unroll
    for (int mt = 0; mt < 2; mt++)
        #pragma unroll
        for (int k = 0; k < 2; k++) {
            int rowA = mg * 32 + mt * 16 + (lane & 15);
            int ch = k * 2 + (lane >> 4);
            int swz = ch ^ ((rowA >> 1) & 3);
            offA[mt][k] = (uint32_t)(rowA * 64 + swz * 16);
        }
    uint32_t offB[2];
    #pragma unroll
    for (int k = 0; k < 2; k++) {
        int rloc = (lane & 7) + ((lane >> 4) << 3);
        int rowB = ng * 64 + rloc;
        int ch = k * 2 + ((lane >> 3) & 1);
        int swz = ch ^ ((rowB >> 1) & 3);
        offB[k] = (uint32_t)(rowB * 64 + swz * 16);
    }

    float s = 0.0f;
    uint32_t af[2][2][4];

    auto compute_tile = [&](int slot, int ti, int tj, bool sym) {
        const uint32_t bb = b_ring + (uint32_t)(slot * 8192);
        uint32_t acc[2][8][2];                      // packed f16x2 accumulators

        bool edge = (ti == NTILES - 1) || (tj == NTILES - 1);
        if (!edge) {
            // ---- full (non-edge) path: identical to R13 ----
            #pragma unroll
            for (int mt = 0; mt < 2; mt++)
                #pragma unroll
                for (int nt = 0; nt < 8; nt++)
                    acc[mt][nt][0] = acc[mt][nt][1] = 0u;
            #pragma unroll
            for (int k = 0; k < 2; k++)
                #pragma unroll
                for (int p = 0; p < 4; p++) {
                    uint32_t b0, b1, b2, b3;
                    ldsm_x4(b0, b1, b2, b3, bb + offB[k] + (uint32_t)(p * 1024));
                    mma_h(acc[0][2*p],   af[0][k], b0, b1);
                    mma_h(acc[0][2*p+1], af[0][k], b2, b3);
                    mma_h(acc[1][2*p],   af[1][k], b0, b1);
                    mma_h(acc[1][2*p+1], af[1][k], b2, b3);
                }
        } else {
            // ---- edge path: issue MMA only for blocks with valid data ----
            bool mv[2];
            #pragma unroll
            for (int mt = 0; mt < 2; mt++)
                mv[mt] = (ti * TILE + mg * 32 + mt * 16) < NPATCH;
            bool nv[8];
            #pragma unroll
            for (int nt = 0; nt < 8; nt++)
                nv[nt] = (tj * TILE + ng * 64 + nt * 8) < NPATCH;
            #pragma unroll
            for (int mt = 0; mt < 2; mt++)
                #pragma unroll
                for (int nt = 0; nt < 8; nt++) {
                    uint32_t init = (mv[mt] && nv[nt]) ? 0u : NEGINF2;
                    acc[mt][nt][0] = init;
                    acc[mt][nt][1] = init;
                }
            #pragma unroll
            for (int k = 0; k < 2; k++)
                #pragma unroll
                for (int p = 0; p < 4; p++) {
                    if (!(nv[2*p] || nv[2*p+1])) continue;
                    uint32_t b0, b1, b2, b3;
                    ldsm_x4(b0, b1, b2, b3, bb + offB[k] + (uint32_t)(p * 1024));
                    if (nv[2*p]) {
                        if (mv[0]) mma_h(acc[0][2*p], af[0][k], b0, b1);
                        if (mv[1]) mma_h(acc[1][2*p], af[1][k], b0, b1);
                    }
                    if (nv[2*p+1]) {
                        if (mv[0]) mma_h(acc[0][2*p+1], af[0][k], b2, b3);
                        if (mv[1]) mma_h(acc[1][2*p+1], af[1][k], b2, b3);
                    }
                }
        }

        bool diagTile = sym && (tj == ti);

        // packed max tree over 32 f16x2 regs (64 args; -inf entries inert)
        uint32_t m16[16];
        #pragma unroll
        for (int mt = 0; mt < 2; mt++)
            #pragma unroll
            for (int nt = 0; nt < 8; nt++)
                m16[mt * 8 + nt] = hmax2u(acc[mt][nt][0], acc[mt][nt][1]);
        #pragma unroll
        for (int st = 8; st > 0; st >>= 1)
            #pragma unroll
            for (int i2 = 0; i2 < 8; i2++)
                if (i2 < st) m16[i2] = hmax2u(m16[i2], m16[i2 + st]);
        __half2 hm = *reinterpret_cast<__half2*>(&m16[0]);
        float mx = fmaxf(__low2float(hm), __high2float(hm));

        if (diagTile || __any_sync(0xffffffffu, mx > -30.0f)) {
            float w = sym ? ((tj == ti) ? 1.0f : 2.0f) : -2.0f;
            int rbase = mg * 32 + (lane >> 2);
            int cbase = ng * 64 + ((lane & 3) << 1);
            float ts = 0.0f;
            #pragma unroll
            for (int mt = 0; mt < 2; mt++)
                #pragma unroll
                for (int nt = 0; nt < 8; nt++)
                    #pragma unroll
                    for (int r = 0; r < 2; r++) {
                        int rl = rbase + mt * 16 + (r << 3);
                        __half2 hv = *reinterpret_cast<__half2*>(&acc[mt][nt][r]);
                        float a0 = __low2float(hv);
                        float a1 = __high2float(hv);
                        int cl0 = cbase + nt * 8;
                        bool ok = (ti * TILE + rl < NPATCH);
                        bool d0 = diagTile && ok && (rl == cl0);
                        bool d1 = diagTile && ok && (rl == cl0 + 1);
                        float e0, e1;
                        asm("ex2.approx.ftz.f32 %0, %1;" : "=f"(e0) : "f"(a0));
                        asm("ex2.approx.ftz.f32 %0, %1;" : "=f"(e1) : "f"(a1));
                        ts += (d0 ? 1.0f : e0) + (d1 ? 1.0f : e1);
                    }
            s = fmaf(w, ts, s);
        }
    };

    // load `cnt` B tiles (tj0b..tj0b+cnt-1) into slots slot0..slot0+cnt-1
    auto loadB = [&](const uint4* bbase, int tj0b, int cnt, int slot0) {
        for (int t = 0; t < cnt; t++) {
            const uint4* bs = bbase + ((tj0b + t) * TILE) * ROW_U4;
            uint32_t dst = b_ring + (uint32_t)((slot0 + t) * 8192);
            cp_async16(dst + (uint32_t)(tid * 16), bs + tid);
            cp_async16(dst + (uint32_t)((tid + 256) * 16), bs + tid + 256);
        }
    };

    for (;;) {
        __syncthreads();
        if (tid == 0) *tkt = atomicAdd(&g_ticket, 1u);
        __syncthreads();
        unsigned int c = *tkt;
        if (c >= CHUNKS) break;

        // ---- decode 8-tile chunk (128x128 tiles) ----
        int ti, tj0, len, verA, verB, b;
        bool sym;
        if (c < 992u) {
            int seg = c >> 2, q = c & 3;
            b = seg / 31; ti = seg - b * 31;
            tj0 = q * 8; len = (q < 3) ? 8 : 7;
            sym = false; verA = 0; verB = 3;
        } else {
            int d = (int)c - 992;
            int g = d / 76;
            int r = d - g * 76;
            int kind = g >> 3; b = g & 7;
            if (r < 8)       { ti = r;              tj0 = 0; }
            else if (r < 24) { int q = r - 8;  ti = 8  + (q >> 1); tj0 = (q & 1) * 8; }
            else if (r < 48) { int q = r - 24; int qd = q / 3; ti = 16 + qd; tj0 = (q - qd * 3) * 8; }
            else             { int q = r - 48; ti = 24 + (q >> 2); tj0 = (q & 3) * 8; }
            len = min(8, ti + 1 - tj0);
            sym = true; verA = kind; verB = 2 + kind;
        }

        const uint4* bbase = g_stage + ((verB * BATCH + b) * NROWS) * ROW_U4;

        // ---- prologue: A + first window (up to 4 B tiles) ----
        {
            const uint4* asrc = g_stage + ((verA * BATCH + b) * NROWS + ti * TILE) * ROW_U4;
            cp_async16(a_base + (uint32_t)(tid * 16), asrc + tid);
            cp_async16(a_base + (uint32_t)((tid + 256) * 16), asrc + tid + 256);
            loadB(bbase, tj0, min(len, 4), 0);
            CP_COMMIT();
        }

        int grp = 0;
        for (int w0 = 0; w0 < len; w0 += 4, grp ^= 1) {
            CP_WAIT0();
            __syncthreads();                 // window data visible; other group free
            int nxt = w0 + 4;
            if (nxt < len) {
                loadB(bbase, tj0 + nxt, min(4, len - nxt), (grp ^ 1) * 4);
                CP_COMMIT();
            }
            if (w0 == 0) {
                #pragma unroll
                for (int mt = 0; mt < 2; mt++)
                    #pragma unroll
                    for (int k = 0; k < 2; k++)
                        ldsm_x4(af[mt][k][0], af[mt][k][1], af[mt][k][2], af[mt][k][3],
                                a_base + offA[mt][k]);
            }
            int s0 = grp * 4;
            int rem = len - w0;
            if (rem >= 4) {                  // straight-line 4 tiles for ILP
                compute_tile(s0,     ti, tj0 + w0,     sym);
                compute_tile(s0 + 1, ti, tj0 + w0 + 1, sym);
                compute_tile(s0 + 2, ti, tj0 + w0 + 2, sym);
                compute_tile(s0 + 3, ti, tj0 + w0 + 3, sym);
            } else {
                for (int t = 0; t < rem; t++)
                    compute_tile(s0 + t, ti, tj0 + w0 + t, sym);
            }
        }
    }

    // ================= Phase 3: reduce + finalize =================
    #pragma unroll
    for (int o = 16; o; o >>= 1) s += __shfl_xor_sync(0xffffffffu, s, o);
    if (lane == 0) red[wid] = s;
    __syncthreads();
    if (tid == 0) {
        float tot = 0.0f;
        #pragma unroll
        for (int i2 = 0; i2 < 8; i2++) tot += red[i2];
        g_partials[blockIdx.x] = tot;
        __threadfence();
        unsigned int old = atomicAdd(&g_done, 1u);
        *lst = (old == WORKERS - 1) ? 1u : 0u;
    }
    __syncthreads();
    if (*lst) {
        __threadfence();
        float v = 0.0f;
        for (int i = tid; i < WORKERS; i += 256) v += g_partials[i];
        #pragma unroll
        for (int o = 16; o; o >>= 1) v += __shfl_xor_sync(0xffffffffu, v, o);
        if (lane == 0) red[wid] = v;
        __syncthreads();
        if (tid == 0) {
            float tot = 0.0f;
            #pragma unroll
            for (int i2 = 0; i2 < 8; i2++) tot += red[i2];
            out[0] = tot * (float)(1.0 / (8.0 * 3844.0 * 3844.0));
            g_bar1 = 0u;
            g_ticket = 0u;
            __threadfence();
            g_done = 0u;
        }
    }
}

extern "C" void kernel_launch(void* const* d_in, const int* in_sizes, int n_in,
                              void* d_out, int out_size) {
    const float* x = (const float*)d_in[0];
    const float* y = (const float*)d_in[1];
    cudaFuncSetAttribute(mmd_fused,
                         cudaFuncAttributeMaxDynamicSharedMemorySize, SMEM_BYTES);
    mmd_fused<<<WORKERS, 256, SMEM_BYTES>>>(x, y, (float*)d_out);
}

// round 16
// speedup vs baseline: 2.4900x; 1.0771x over previous
#include <cuda_runtime.h>
#include <cuda_fp16.h>
#include <cstdint>

// GlobalPoolDistance: patch-RBF MMD, single fused persistent kernel (R16).
// f16 mma.sync m16n8k16 (f16 accumulate) computes the exp2 argument directly:
//   A row i = [C2*a_0..C2*a_26, 1, -u_i, 0..]   (u = ||a||^2 * log2e/SIG2)
//   B row j = [b_0..b_26,      -v_j, 1, 0..]
//   acc(i,j) = C2*<a,b> - u - v = -log2e*||a-b||^2/SIG2 ; K = exp2(acc).
// Epilogue skip threshold -30 (deterministic per-term bound, see R7);
// diagonal tiles force the epilogue; diagonals replaced by exact 1.0.
// R16: chunk-level edge partition. Interior chunks (ti,tj <= 29) run the
// exact R13 hot body with NO edge branch. All index-30 tiles live in 128
// dedicated edge chunks; the xy column strip (ti<30, tj=30) is transposed
// into a row strip via A-form y[30] x B-form x (all 4 forms are staged).
// Edge tiles have only 4 valid A rows -> only mg==0 warps issue MMAs.

#define TILE 128
#define NPATCH 3844
#define NTILES 31
#define NROWS (NTILES * TILE)                     // 3968
#define BATCH 8
#define ROW_U4 4                                  // 64 B per staged row (32 f16)
#define STAGE_U4 (4 * BATCH * NROWS * ROW_U4)
#define CHUNKS 2240        // 960 int-xy + 1152 int-sym + 64 edge-xy + 64 edge-sym
#define WORKERS 296
#define STAGE_TASKS (2 * BATCH * NROWS)           // 63488

// dynamic smem layout
#define SMEM_A_OFF   0                            // 8 KB A tile
#define SMEM_B_OFF   8192                         // 8 slots x 8 KB
#define SMEM_RED_OFF (8192 + 8 * 8192)            // 73728
#define SMEM_TKT_OFF (SMEM_RED_OFF + 32)
#define SMEM_LST_OFF (SMEM_TKT_OFF + 4)
#define SMEM_BYTES   (SMEM_LST_OFF + 4 + 24)

__device__ uint4 g_stage[STAGE_U4];
__device__ float g_partials[WORKERS];
__device__ unsigned int g_bar1;
__device__ unsigned int g_ticket;
__device__ unsigned int g_done;

__device__ __forceinline__ uint32_t smem_to_u32(const void* p) {
    uint32_t a;
    asm("{ .reg .u64 t; cvta.to.shared.u64 t, %1; cvt.u32.u64 %0, t; }"
        : "=r"(a) : "l"(p));
    return a;
}
__device__ __forceinline__ void cp_async16(uint32_t smem, const void* gptr) {
    asm volatile("cp.async.cg.shared.global [%0], [%1], 16;"
                 :: "r"(smem), "l"(gptr) : "memory");
}
#define CP_COMMIT() asm volatile("cp.async.commit_group;" ::: "memory")
#define CP_WAIT0()  asm volatile("cp.async.wait_group 0;" ::: "memory")

__device__ __forceinline__ void ldsm_x4(uint32_t& r0, uint32_t& r1,
                                        uint32_t& r2, uint32_t& r3, uint32_t a) {
    asm volatile("ldmatrix.sync.aligned.m8n8.x4.shared.b16 {%0,%1,%2,%3}, [%4];"
                 : "=r"(r0), "=r"(r1), "=r"(r2), "=r"(r3) : "r"(a));
}
// f16 MMA with f16 accumulate: C fragment = 2 packed f16x2 regs.
__device__ __forceinline__ void mma_h(uint32_t* d, const uint32_t* a,
                                      uint32_t b0, uint32_t b1) {
    asm volatile("mma.sync.aligned.m16n8k16.row.col.f16.f16.f16.f16 "
                 "{%0,%1}, {%2,%3,%4,%5}, {%6,%7}, {%0,%1};"
                 : "+r"(d[0]), "+r"(d[1])
                 : "r"(a[0]), "r"(a[1]), "r"(a[2]), "r"(a[3]), "r"(b0), "r"(b1));
}
__device__ __forceinline__ uint32_t pkh(float a, float b) {
    __half2 h = __floats2half2_rn(a, b);
    return *reinterpret_cast<uint32_t*>(&h);
}
__device__ __forceinline__ uint32_t hmax2u(uint32_t a, uint32_t b) {
    __half2 r = __hmax2(*reinterpret_cast<__half2*>(&a),
                        *reinterpret_cast<__half2*>(&b));
    return *reinterpret_cast<uint32_t*>(&r);
}

extern __shared__ __align__(1024) char dsm[];

__global__ void __launch_bounds__(256, 2)
mmd_fused(const float* __restrict__ x, const float* __restrict__ y,
          float* __restrict__ out) {
    const int tid = threadIdx.x;
    const int wid = tid >> 5;
    const int lane = tid & 31;

    float* red = reinterpret_cast<float*>(dsm + SMEM_RED_OFF);
    unsigned int* tkt = reinterpret_cast<unsigned int*>(dsm + SMEM_TKT_OFF);
    unsigned int* lst = reinterpret_cast<unsigned int*>(dsm + SMEM_LST_OFF);

    const float K1f = 4.9479492581208223f;        // log2e / 0.2916
    const float C2f = 9.8958985162416446f;        // 2*log2e / 0.2916

    // ================= Phase 1: stage f16 operand rows =================
    {
        int gtid = blockIdx.x * 256 + tid;
        if (gtid < STAGE_TASKS) {
            int n = gtid % NROWS;
            int t2 = gtid / NROWS;
            int b = t2 & 7;
            int img = t2 >> 3;
            const float* im = img ? y : x;

            float rv[27];
            float u = 0.0f;
            bool valid = (n < NPATCH);
            if (valid) {
                int i = n / 62;
                int j = n - i * 62;
                const float* p = im + b * 12288 + (i << 6) + j;
                float sq = 0.0f;
                #pragma unroll
                for (int c = 0; c < 3; c++)
                    #pragma unroll
                    for (int rr = 0; rr < 3; rr++)
                        #pragma unroll
                        for (int ss = 0; ss < 3; ss++) {
                            float v = p[c * 4096 + (rr << 6) + ss];
                            sq = fmaf(v, v, sq);
                            rv[c * 9 + rr * 3 + ss] = v;
                        }
                u = sq * K1f;
            } else {
                #pragma unroll
                for (int k = 0; k < 27; k++) rv[k] = 0.0f;
            }
            uint32_t sw = (uint32_t)(n >> 1) & 3u;

            #pragma unroll
            for (int form = 0; form < 2; form++) {
                float rowv[32];
                #pragma unroll
                for (int k = 0; k < 27; k++)
                    rowv[k] = form ? rv[k] : (C2f * rv[k]);
                float nu = valid ? -u : -60000.0f;   // fp16-range pad sentinel
                if (form) { rowv[27] = nu;   rowv[28] = 1.0f; }
                else      { rowv[27] = 1.0f; rowv[28] = nu;   }
                rowv[29] = rowv[30] = rowv[31] = 0.0f;
                uint32_t wds[16];
                #pragma unroll
                for (int q = 0; q < 16; q++)
                    wds[q] = pkh(rowv[2*q], rowv[2*q+1]);
                int ver = form * 2 + img;
                int base = ((ver * BATCH + b) * NROWS + n) * ROW_U4;
                #pragma unroll
                for (int c = 0; c < 4; c++)
                    g_stage[base + (c ^ sw)] =
                        make_uint4(wds[4*c], wds[4*c+1], wds[4*c+2], wds[4*c+3]);
            }
        }
        __threadfence();
        __syncthreads();
        if (tid == 0) {
            atomicAdd(&g_bar1, 1u);
            unsigned int v;
            do {
                asm volatile("ld.acquire.gpu.global.u32 %0, [%1];"
                             : "=r"(v) : "l"(&g_bar1));
                if (v >= WORKERS) break;
                __nanosleep(64);
            } while (true);
        }
        __syncthreads();
        __threadfence();
    }

    // ================= Phase 2: persistent tile loop =================
    const int mg = wid & 3;          // A rows mg*32..+31
    const int ng = wid >> 2;         // B rows ng*64..+63
    const uint32_t a_base = smem_to_u32(dsm) + SMEM_A_OFF;
    const uint32_t b_ring = smem_to_u32(dsm) + SMEM_B_OFF;   // 8 x 8192 B

    uint32_t offA[2][2];
    #pragma unroll
    for (int mt = 0; mt < 2; mt++)
        #pragma unroll
        for (int k = 0; k < 2; k++) {
            int rowA = mg * 32 + mt * 16 + (lane & 15);
            int ch = k * 2 + (lane >> 4);
            int swz = ch ^ ((rowA >> 1) & 3);
            offA[mt][k] = (uint32_t)(rowA * 64 + swz * 16);
        }
    uint32_t offB[2];
    #pragma unroll
    for (int k = 0; k < 2; k++) {
        int rloc = (lane & 7) + ((lane >> 4) << 3);
        int rowB = ng * 64 + rloc;
        int ch = k * 2 + ((lane >> 3) & 1);
        int swz = ch ^ ((rowB >> 1) & 3);
        offB[k] = (uint32_t)(rowB * 64 + swz * 16);
    }

    float s = 0.0f;
    uint32_t af[2][2][4];

    // ---- interior tile: EXACT R13 body (no edge logic) ----
    auto compute_tile = [&](int slot, int ti, int tj, bool sym) {
        const uint32_t bb = b_ring + (uint32_t)(slot * 8192);
        uint32_t acc[2][8][2];
        #pragma unroll
        for (int mt = 0; mt < 2; mt++)
            #pragma unroll
            for (int nt = 0; nt < 8; nt++)
                acc[mt][nt][0] = acc[mt][nt][1] = 0u;

        #pragma unroll
        for (int k = 0; k < 2; k++)
            #pragma unroll
            for (int p = 0; p < 4; p++) {
                uint32_t b0, b1, b2, b3;
                ldsm_x4(b0, b1, b2, b3, bb + offB[k] + (uint32_t)(p * 1024));
                mma_h(acc[0][2*p],   af[0][k], b0, b1);
                mma_h(acc[0][2*p+1], af[0][k], b2, b3);
                mma_h(acc[1][2*p],   af[1][k], b0, b1);
                mma_h(acc[1][2*p+1], af[1][k], b2, b3);
            }

        bool diagTile = sym && (tj == ti);

        uint32_t m16[16];
        #pragma unroll
        for (int mt = 0; mt < 2; mt++)
            #pragma unroll
            for (int nt = 0; nt < 8; nt++)
                m16[mt * 8 + nt] = hmax2u(acc[mt][nt][0], acc[mt][nt][1]);
        #pragma unroll
        for (int st = 8; st > 0; st >>= 1)
            #pragma unroll
            for (int i2 = 0; i2 < 8; i2++)
                if (i2 < st) m16[i2] = hmax2u(m16[i2], m16[i2 + st]);
        __half2 hm = *reinterpret_cast<__half2*>(&m16[0]);
        float mx = fmaxf(__low2float(hm), __high2float(hm));

        if (diagTile || __any_sync(0xffffffffu, mx > -30.0f)) {
            float w = sym ? ((tj == ti) ? 1.0f : 2.0f) : -2.0f;
            int rbase = mg * 32 + (lane >> 2);
            int cbase = ng * 64 + ((lane & 3) << 1);
            float ts = 0.0f;
            #pragma unroll
            for (int mt = 0; mt < 2; mt++)
                #pragma unroll
                for (int nt = 0; nt < 8; nt++)
                    #pragma unroll
                    for (int r = 0; r < 2; r++) {
                        int rl = rbase + mt * 16 + (r << 3);
                        __half2 hv = *reinterpret_cast<__half2*>(&acc[mt][nt][r]);
                        float a0 = __low2float(hv);
                        float a1 = __high2float(hv);
                        int cl0 = cbase + nt * 8;
                        bool d0 = diagTile && (rl == cl0);      // interior: all rows valid
                        bool d1 = diagTile && (rl == cl0 + 1);
                        float e0, e1;
                        asm("ex2.approx.ftz.f32 %0, %1;" : "=f"(e0) : "f"(a0));
                        asm("ex2.approx.ftz.f32 %0, %1;" : "=f"(e1) : "f"(a1));
                        ts += (d0 ? 1.0f : e0) + (d1 ? 1.0f : e1);
                    }
            s = fmaf(w, ts, s);
        }
    };

    // ---- edge tile (A tile = index 30, only 4 valid rows): mg==0 warps only ----
    auto compute_edge = [&](int slot, int tj, bool symE) {
        if (mg != 0) return;                 // rows 32..127 of tile are all pad
        bool colE = (tj == NTILES - 1);      // <=4 valid B cols too
        if (colE && ng != 0) return;
        const uint32_t bb = b_ring + (uint32_t)(slot * 8192);
        uint32_t acc[8][2];
        int ntN = colE ? 1 : 8;
        for (int nt = 0; nt < ntN; nt++) acc[nt][0] = acc[nt][1] = 0u;

        for (int k = 0; k < 2; k++) {
            int pN = colE ? 1 : 4;
            for (int p = 0; p < pN; p++) {
                uint32_t b0, b1, b2, b3;
                ldsm_x4(b0, b1, b2, b3, bb + offB[k] + (uint32_t)(p * 1024));
                mma_h(acc[2*p], af[0][k], b0, b1);
                if (!colE) mma_h(acc[2*p+1], af[0][k], b2, b3);
            }
        }

        bool diagTile = symE && colE;        // ti==tj==30
        uint32_t mT = acc[0][0];
        for (int nt = 0; nt < ntN; nt++) {
            mT = hmax2u(mT, acc[nt][0]);
            mT = hmax2u(mT, acc[nt][1]);
        }
        __half2 hm = *reinterpret_cast<__half2*>(&mT);
        float mx = fmaxf(__low2float(hm), __high2float(hm));

        if (diagTile || __any_sync(0xffffffffu, mx > -30.0f)) {
            float w = symE ? (colE ? 1.0f : 2.0f) : -2.0f;
            int rbase = (lane >> 2);         // mg=0, mt=0
            int cbase = ng * 64 + ((lane & 3) << 1);
            float ts = 0.0f;
            for (int nt = 0; nt < ntN; nt++)
                for (int r = 0; r < 2; r++) {
                    int rl = rbase + (r << 3);
                    __half2 hv = *reinterpret_cast<__half2*>(&acc[nt][r]);
                    float a0 = __low2float(hv);
                    float a1 = __high2float(hv);
                    int cl0 = cbase + nt * 8;
                    bool ok = (rl < 4);      // 3840 + rl < 3844
                    bool d0 = diagTile && ok && (rl == cl0);
                    bool d1 = diagTile && ok && (rl == cl0 + 1);
                    float e0, e1;
                    asm("ex2.approx.ftz.f32 %0, %1;" : "=f"(e0) : "f"(a0));
                    asm("ex2.approx.ftz.f32 %0, %1;" : "=f"(e1) : "f"(a1));
                    ts += (d0 ? 1.0f : e0) + (d1 ? 1.0f : e1);
                }
            s = fmaf(w, ts, s);
        }
    };

    // load `cnt` B tiles (tj0b..) into ring slots slot0..
    auto loadB = [&](const uint4* bbase, int tj0b, int cnt, int slot0) {
        for (int t = 0; t < cnt; t++) {
            const uint4* bs = bbase + ((tj0b + t) * TILE) * ROW_U4;
            uint32_t dst = b_ring + (uint32_t)((slot0 + t) * 8192);
            cp_async16(dst + (uint32_t)(tid * 16), bs + tid);
            cp_async16(dst + (uint32_t)((tid + 256) * 16), bs + tid + 256);
        }
    };

    for (;;) {
        __syncthreads();
        if (tid == 0) *tkt = atomicAdd(&g_ticket, 1u);
        __syncthreads();
        unsigned int c = *tkt;
        if (c >= CHUNKS) break;

        // ---- decode chunk ----
        int ti, tj0, len, verA, verB, b, atile;
        bool sym, edgeMode;
        if (c < 960u) {
            // interior xy: ti 0..29, tj 0..29
            int seg = c >> 2, q = c & 3;
            b = seg / 30; ti = seg - b * 30;
            tj0 = q * 8; len = (q < 3) ? 8 : 6;
            sym = false; edgeMode = false; verA = 0; verB = 3; atile = ti;
        } else if (c < 2112u) {
            // interior sym: ti 0..29 triangle
            int d = (int)c - 960;
            int g = d / 72;
            int r = d - g * 72;
            int kind = g >> 3; b = g & 7;
            if (r < 8)       { ti = r;              tj0 = 0; }
            else if (r < 24) { int q = r - 8;  ti = 8  + (q >> 1); tj0 = (q & 1) * 8; }
            else if (r < 48) { int q = r - 24; int qd = q / 3; ti = 16 + qd; tj0 = (q - qd * 3) * 8; }
            else             { int q = r - 48; ti = 24 + (q >> 2); tj0 = (q & 3) * 8; }
            len = min(8, ti + 1 - tj0);
            sym = true; edgeMode = false; verA = kind; verB = 2 + kind; atile = ti;
        } else if (c < 2176u) {
            // xy edge strips: strip0 A=x[30] vs all y tiles (incl 30);
            //                 strip1 A=y[30] vs x tiles 0..29 (transposed column)
            int d = (int)c - 2112;
            b = d >> 3;
            int e = d & 7;
            int strip = e >> 2, q = e & 3;
            tj0 = q * 8;
            len = (q < 3) ? 8 : (strip == 0 ? 7 : 6);
            verA = strip ? 1 : 0; verB = strip ? 2 : 3;
            ti = NTILES - 1; atile = NTILES - 1;
            sym = false; edgeMode = true;
        } else {
            // sym edge: ti=30 strip, tj 0..30
            int d = (int)c - 2176;
            int g = d >> 2, q = d & 3;
            int kind = g >> 3; b = g & 7;
            verA = kind; verB = 2 + kind;
            tj0 = q * 8; len = (q < 3) ? 8 : 7;
            ti = NTILES - 1; atile = NTILES - 1;
            sym = true; edgeMode = true;
        }

        const uint4* bbase = g_stage + ((verB * BATCH + b) * NROWS) * ROW_U4;

        // ---- prologue: A + first window (up to 4 B tiles) ----
        {
            const uint4* asrc = g_stage + ((verA * BATCH + b) * NROWS + atile * TILE) * ROW_U4;
            cp_async16(a_base + (uint32_t)(tid * 16), asrc + tid);
            cp_async16(a_base + (uint32_t)((tid + 256) * 16), asrc + tid + 256);
            loadB(bbase, tj0, min(len, 4), 0);
            CP_COMMIT();
        }

        int grp = 0;
        for (int w0 = 0; w0 < len; w0 += 4, grp ^= 1) {
            CP_WAIT0();
            __syncthreads();                 // window data visible; other group free
            int nxt = w0 + 4;
            if (nxt < len) {
                loadB(bbase, tj0 + nxt, min(4, len - nxt), (grp ^ 1) * 4);
                CP_COMMIT();
            }
            if (w0 == 0) {
                #pragma unroll
                for (int mt = 0; mt < 2; mt++)
                    #pragma unroll
                    for (int k = 0; k < 2; k++)
                        ldsm_x4(af[mt][k][0], af[mt][k][1], af[mt][k][2], af[mt][k][3],
                                a_base + offA[mt][k]);
            }
            int s0 = grp * 4;
            int rem = len - w0;
            if (!edgeMode) {
                if (rem >= 4) {              // straight-line 4 tiles for ILP
                    compute_tile(s0,     ti, tj0 + w0,     sym);
                    compute_tile(s0 + 1, ti, tj0 + w0 + 1, sym);
                    compute_tile(s0 + 2, ti, tj0 + w0 + 2, sym);
                    compute_tile(s0 + 3, ti, tj0 + w0 + 3, sym);
                } else {
                    for (int t = 0; t < rem; t++)
                        compute_tile(s0 + t, ti, tj0 + w0 + t, sym);
                }
            } else {
                int n4 = rem < 4 ? rem : 4;
                for (int t = 0; t < n4; t++)
                    compute_edge(s0 + t, tj0 + w0 + t, sym);
            }
        }
    }

    // ================= Phase 3: reduce + finalize =================
    #pragma unroll
    for (int o = 16; o; o >>= 1) s += __shfl_xor_sync(0xffffffffu, s, o);
    if (lane == 0) red[wid] = s;
    __syncthreads();
    if (tid == 0) {
        float tot = 0.0f;
        #pragma unroll
        for (int i2 = 0; i2 < 8; i2++) tot += red[i2];
        g_partials[blockIdx.x] = tot;
        __threadfence();
        unsigned int old = atomicAdd(&g_done, 1u);
        *lst = (old == WORKERS - 1) ? 1u : 0u;
    }
    __syncthreads();
    if (*lst) {
        __threadfence();
        float v = 0.0f;
        for (int i = tid; i < WORKERS; i += 256) v += g_partials[i];
        #pragma unroll
        for (int o = 16; o; o >>= 1) v += __shfl_xor_sync(0xffffffffu, v, o);
        if (lane == 0) red[wid] = v;
        __syncthreads();
        if (tid == 0) {
            float tot = 0.0f;
            #pragma unroll
            for (int i2 = 0; i2 < 8; i2++) tot += red[i2];
            out[0] = tot * (float)(1.0 / (8.0 * 3844.0 * 3844.0));
            g_bar1 = 0u;
            g_ticket = 0u;
            __threadfence();
            g_done = 0u;
        }
    }
}

extern "C" void kernel_launch(void* const* d_in, const int* in_sizes, int n_in,
                              void* d_out, int out_size) {
    const float* x = (const float*)d_in[0];
    const float* y = (const float*)d_in[1];
    cudaFuncSetAttribute(mmd_fused,
                         cudaFuncAttributeMaxDynamicSharedMemorySize, SMEM_BYTES);
    mmd_fused<<<WORKERS, 256, SMEM_BYTES>>>(x, y, (float*)d_out);
}